// round 3
// baseline (speedup 1.0000x reference)
#include <cuda_runtime.h>
#include <cfloat>

#define SPATIAL_SCALE 0.0625f
#define NN 2
#define CC 256
#define HH 64
#define WW 64
#define KK 128
#define PH 7
#define PW 7

__global__ void roipool_kernel(const float* __restrict__ x,
                               const float* __restrict__ rois,
                               float* __restrict__ out,
                               int total) {
    int idx = blockIdx.x * blockDim.x + threadIdx.x;
    if (idx >= total) return;

    int pw = idx % PW;
    int ph = (idx / PW) % PH;
    int c  = (idx / (PW * PH)) % CC;
    int k  = idx / (PW * PH * CC);

    const float* r = rois + k * 5;
    int b  = (int)__ldg(&r[0]);
    // exact product (x * 2^-4), rintf = round-half-even = jnp.round
    int x1 = (int)rintf(__ldg(&r[1]) * SPATIAL_SCALE);
    int y1 = (int)rintf(__ldg(&r[2]) * SPATIAL_SCALE);
    int x2 = (int)rintf(__ldg(&r[3]) * SPATIAL_SCALE);
    int y2 = (int)rintf(__ldg(&r[4]) * SPATIAL_SCALE);

    int roi_w = max(x2 - x1 + 1, 1);
    int roi_h = max(y2 - y1 + 1, 1);

    // Hypothesis: reference (XLA) lowers /7 to multiply-by-reciprocal.
    // fl(1/7) = 0x3E124925 (rounds high). Pin all arithmetic with _rn intrinsics.
    const float INV7 = __uint_as_float(0x3E124925u);
    float bw = __fmul_rn((float)roi_w, INV7);
    float bh = __fmul_rn((float)roi_h, INV7);

    int ws = (int)floorf(__fmul_rn((float)pw, bw)) + x1;
    int we = (int)ceilf(__fmul_rn((float)(pw + 1), bw)) + x1;
    int hs = (int)floorf(__fmul_rn((float)ph, bh)) + y1;
    int he = (int)ceilf(__fmul_rn((float)(ph + 1), bh)) + y1;

    ws = min(max(ws, 0), WW);
    we = min(max(we, 0), WW);
    hs = min(max(hs, 0), HH);
    he = min(max(he, 0), HH);

    float m;
    if (hs >= he || ws >= we) {
        m = 0.0f;
    } else {
        m = -FLT_MAX;
        const float* plane = x + ((long)b * CC + c) * (HH * WW);
        for (int h = hs; h < he; ++h) {
            const float* row = plane + h * WW;
            for (int w = ws; w < we; ++w) {
                m = fmaxf(m, __ldg(&row[w]));
            }
        }
    }
    out[idx] = m;
}

extern "C" void kernel_launch(void* const* d_in, const int* in_sizes, int n_in,
                              void* d_out, int out_size) {
    // Bind inputs by size for robustness: rois has 128*5 = 640 elements.
    const float* x    = (const float*)d_in[0];
    const float* rois = (const float*)d_in[1];
    if (n_in >= 2 && in_sizes[0] == KK * 5) {
        x    = (const float*)d_in[1];
        rois = (const float*)d_in[0];
    }
    float* out = (float*)d_out;
    int total = KK * CC * PH * PW;
    int threads = 256;
    int blocks = (total + threads - 1) / threads;
    roipool_kernel<<<blocks, threads>>>(x, rois, out, total);
}